// round 11
// baseline (speedup 1.0000x reference)
#include <cuda_runtime.h>
#include <cuda_fp16.h>
#include <cstdint>

#define B_ 4
#define T_ 4096
#define C_ 1024
#define H_ 64
#define NCH 8  // max split-K chunks per q-tile

// Scratch (static __device__, allocation-free per harness rules).
// All fp16 operand arrays use word-level pair permutation: within each group
// of 8 half2-words (16 halves), logical word j is stored at 2j (j<4) / 2j-7.
__device__ uint32_t g_q[B_ * T_ * 32];   // q/32, half2 words [row][32]
__device__ uint32_t g_k[B_ * T_ * 32];   // k, half2 words [key][32]
__device__ __half g_vt[(size_t)B_ * H_ * T_];  // v transposed [b][h][s]
__device__ uint32_t g_wt[3][H_ * (C_ / 2)];    // W^T [n][k-words]
__device__ float g_opart[NCH][B_ * T_ * H_];   // partial O per chunk (fp32)
__device__ float g_lpart[NCH][B_ * T_];        // exp-sum per chunk

// ---------------------------------------------------------------------------
// Helpers (generic PTX — compiles on compute_103 target)
// ---------------------------------------------------------------------------
__device__ __forceinline__ uint32_t smem_u32(const void* p) {
  uint32_t a;
  asm("{ .reg .u64 t; cvta.to.shared.u64 t, %1; cvt.u32.u64 %0, t; }"
      : "=r"(a) : "l"(p));
  return a;
}
__device__ __forceinline__ uint32_t pack2(float lo, float hi) {
  __half2 h = __floats2half2_rn(lo, hi);
  return *reinterpret_cast<uint32_t*>(&h);
}
__device__ __forceinline__ int pj(int j) {  // word perm within 8-word group
  return (j < 4) ? (j << 1) : ((j << 1) - 7);
}
#define CP_ASYNC16(dst, src) \
  asm volatile("cp.async.cg.shared.global [%0], [%1], 16;" :: "r"(dst), "l"(src))
#define CP_COMMIT() asm volatile("cp.async.commit_group;" ::: "memory")
#define CP_WAIT(n) asm volatile("cp.async.wait_group %0;" :: "n"(n) : "memory")

// D(m16n8) += A(m16k16,row) * B(k16n8,col), fp16 inputs, f32 accum.
// A: a0=(g, k=2t,2t+1) a1=(g+8, same) a2=(g, 2t+8,2t+9) a3=(g+8, same)
// B: b0=(k=2t,2t+1, n=g) b1=(k=2t+8,2t+9, n=g)
// C: c0=(g,2t) c1=(g,2t+1) c2=(g+8,2t) c3=(g+8,2t+1)   [g=lane>>2, t=lane&3]
__device__ __forceinline__ void mma16(float* c, const uint32_t* a, uint2 b) {
  asm volatile(
      "mma.sync.aligned.m16n8k16.row.col.f32.f16.f16.f32 "
      "{%0,%1,%2,%3}, {%4,%5,%6,%7}, {%8,%9}, {%0,%1,%2,%3};"
      : "+f"(c[0]), "+f"(c[1]), "+f"(c[2]), "+f"(c[3])
      : "r"(a[0]), "r"(a[1]), "r"(a[2]), "r"(a[3]), "r"(b.x), "r"(b.y));
}

// ---------------------------------------------------------------------------
// Weight prep: g_wt[wsel][n][kw] = fp16(W[k][n]), pair-permuted words.
// ---------------------------------------------------------------------------
__global__ __launch_bounds__(256) void wcvt_kernel(
    const float* __restrict__ Wq, const float* __restrict__ Wk,
    const float* __restrict__ Wv) {
  int idx = blockIdx.x * 256 + threadIdx.x;
  int wsel = idx >> 12;
  int rem = idx & 4095;
  int gk = rem >> 6;     // k-group (16 k's)
  int n = rem & 63;
  const float* W = (wsel == 0) ? Wq : ((wsel == 1) ? Wk : Wv);
  uint32_t wl[8];
#pragma unroll
  for (int j = 0; j < 8; j++)
    wl[j] = pack2(W[(size_t)(gk * 16 + 2 * j) * H_ + n],
                  W[(size_t)(gk * 16 + 2 * j + 1) * H_ + n]);
  uint4 lo = make_uint4(wl[0], wl[4], wl[1], wl[5]);
  uint4 hi = make_uint4(wl[2], wl[6], wl[3], wl[7]);
  *(uint4*)&g_wt[wsel][(size_t)n * 512 + gk * 8] = lo;
  *(uint4*)&g_wt[wsel][(size_t)n * 512 + gk * 8 + 4] = hi;
}

// ---------------------------------------------------------------------------
// Projection: {q,k,v} = x @ {Wq,Wk,Wv}, fp16 m16n8k16. CTA 64(M) x 192(N),
// K chunks of 64 (16 chunks). W via cp.async from g_wt; x reg-prefetched,
// converted+packed once per element. 8 warps = 2(M) x 4(N); warp tile 32x48.
// Smem word stride 40 (≡8 mod 32 -> conflict-free LDS.64 per 16-lane phase).
// ---------------------------------------------------------------------------
#define SSTR 40
#define PJ_XS (64 * SSTR)           // 2560 u32
#define PJ_ST (PJ_XS + 192 * SSTR) // 10240 u32 per stage
#define PJ_SMEM (2 * PJ_ST * 4)    // 81920 B

__global__ __launch_bounds__(256, 2) void proj_kernel(
    const float* __restrict__ x) {
  extern __shared__ uint32_t sm[];
  const uint32_t smb = smem_u32(sm);

  const int tid = threadIdx.x;
  const int lane = tid & 31;
  const int w = tid >> 5;
  const int g = lane >> 2, t = lane & 3;
  const int wm = (w & 1) << 5;   // warp M offset (0,32)
  const int wn = (w >> 1) * 48;  // warp N offset (0,48,96,144)
  const int row0 = blockIdx.x * 64;

  // x staging: thread -> (row, 16k-group gi); 4 float4 per chunk
  const int xrow = tid >> 2, gi = tid & 3;
  const float* xsrc = &x[(size_t)(row0 + xrow) * C_ + gi * 16];
  // W staging: 192 n x 8 u4 = 1536 u4, 6 per thread
  int wofs[6];
  const uint32_t* wsrc[6];
#pragma unroll
  for (int i = 0; i < 6; i++) {
    int fi = tid + (i << 8);
    int n = fi >> 3;
    int w4 = (fi & 7) << 2;
    wofs[i] = n * SSTR + w4;
    wsrc[i] = &g_wt[n >> 6][(size_t)(n & 63) * 512 + w4];
  }

  float4 xv[4];
  auto prefx = [&](int ch) {
#pragma unroll
    for (int i = 0; i < 4; i++)
      xv[i] = *(const float4*)(xsrc + (ch << 6) + (i << 2));
  };
  auto stageW = [&](int ch, int st) {
    const uint32_t wb = smb + (st * PJ_ST + PJ_XS) * 4;
#pragma unroll
    for (int i = 0; i < 6; i++)
      CP_ASYNC16(wb + wofs[i] * 4, wsrc[i] + (ch << 5));
    CP_COMMIT();
  };

  float acc[2][6][4] = {};

  stageW(0, 0);
  prefx(0);
  for (int ch = 0; ch < 16; ch++) {
    const int st = ch & 1;
    uint32_t* Xs = sm + st * PJ_ST;
    uint32_t* Ws = Xs + PJ_XS;
    // convert+pack x once, store permuted
    {
      uint32_t wl[8];
      wl[0] = pack2(xv[0].x, xv[0].y); wl[1] = pack2(xv[0].z, xv[0].w);
      wl[2] = pack2(xv[1].x, xv[1].y); wl[3] = pack2(xv[1].z, xv[1].w);
      wl[4] = pack2(xv[2].x, xv[2].y); wl[5] = pack2(xv[2].z, xv[2].w);
      wl[6] = pack2(xv[3].x, xv[3].y); wl[7] = pack2(xv[3].z, xv[3].w);
      *(uint4*)&Xs[xrow * SSTR + gi * 8] =
          make_uint4(wl[0], wl[4], wl[1], wl[5]);
      *(uint4*)&Xs[xrow * SSTR + gi * 8 + 4] =
          make_uint4(wl[2], wl[6], wl[3], wl[7]);
    }
    CP_WAIT(0);  // W(ch) landed
    __syncthreads();
    if (ch + 1 < 16) {
      stageW(ch + 1, st ^ 1);  // safe: all warps passed barrier
      prefx(ch + 1);
    }

#pragma unroll
    for (int ks = 0; ks < 4; ks++) {
      uint32_t a[2][4];
#pragma unroll
      for (int mb = 0; mb < 2; mb++) {
        int r = wm + (mb << 4) + g;
        uint2 lo = *(const uint2*)&Xs[r * SSTR + (ks << 3) + (t << 1)];
        uint2 hi = *(const uint2*)&Xs[(r + 8) * SSTR + (ks << 3) + (t << 1)];
        a[mb][0] = lo.x; a[mb][1] = hi.x; a[mb][2] = lo.y; a[mb][3] = hi.y;
      }
#pragma unroll
      for (int nb = 0; nb < 6; nb++) {
        uint2 bb = *(const uint2*)&Ws[(wn + (nb << 3) + g) * SSTR +
                                      (ks << 3) + (t << 1)];
        mma16(acc[0][nb], a[0], bb);
        mma16(acc[1][nb], a[1], bb);
      }
    }
  }

  // Epilogue
#pragma unroll
  for (int mb = 0; mb < 2; mb++) {
#pragma unroll
    for (int nb = 0; nb < 6; nb++) {
      int n = wn + (nb << 3) + (t << 1);
      int r = row0 + wm + (mb << 4) + g;
      float c0 = acc[mb][nb][0], c1 = acc[mb][nb][1];
      float c2 = acc[mb][nb][2], c3 = acc[mb][nb][3];
      if (n < 64) {  // q: scaled 1/32
        int wl = n >> 1;
        int sw = (wl & ~7) + pj(wl & 7);
        g_q[(size_t)r * 32 + sw] = pack2(c0 * 0.03125f, c1 * 0.03125f);
        g_q[(size_t)(r + 8) * 32 + sw] = pack2(c2 * 0.03125f, c3 * 0.03125f);
      } else if (n < 128) {  // k
        int wl = (n - 64) >> 1;
        int sw = (wl & ~7) + pj(wl & 7);
        g_k[(size_t)r * 32 + sw] = pack2(c0, c1);
        g_k[(size_t)(r + 8) * 32 + sw] = pack2(c2, c3);
      } else {  // v transposed [b][h][s], permuted s-words
        int h = n - 128;
        int b = r >> 12, s = r & (T_ - 1);
        int wl = s >> 1, sw = (wl & ~7) + pj(wl & 7);
        int s2 = s + 8, wl2 = s2 >> 1, sw2 = (wl2 & ~7) + pj(wl2 & 7);
        size_t hb0 = ((size_t)b * H_ + h) * 2048;
        size_t hb1 = ((size_t)b * H_ + h + 1) * 2048;
        g_vt[(hb0 + sw) * 2 + (s & 1)] = __float2half_rn(c0);
        g_vt[(hb1 + sw) * 2 + (s & 1)] = __float2half_rn(c1);
        g_vt[(hb0 + sw2) * 2 + (s2 & 1)] = __float2half_rn(c2);
        g_vt[(hb1 + sw2) * 2 + (s2 & 1)] = __float2half_rn(c3);
      }
    }
  }
}

// ---------------------------------------------------------------------------
// Split-K causal attention, fp16 m16n8k16, cp.async double-buffered KV.
// CTA: 128 q-rows (8 warps x 16 rows). KV tiles of 128 keys; chunks of
// 4 tiles (512 keys; chunk count (qt+4)>>2 == old (2qt+9)>>3, grid 144 x 4).
// Per tile: 8 x 16-key superblocks, each 8 S-MMA -> exp/mask -> pack -> 8
// O-MMA. Syncs per key halved vs 64-key tiles.
// ---------------------------------------------------------------------------
#define AT_KW 40                      // K row stride (32 words + 8)
#define AT_VW 72                      // V row stride (64 words + 8)
#define AT_KS (128 * AT_KW)           // 5120 u32
#define AT_ST (AT_KS + 64 * AT_VW)    // 9728 u32 per stage
#define AT_SMEM (2 * AT_ST * 4)       // 77824 B

__global__ __launch_bounds__(256, 2) void attn_kernel() {
  extern __shared__ uint32_t sm[];
  const uint32_t smb = smem_u32(sm);

  const int tid = threadIdx.x;
  const int lane = tid & 31;
  const int w = tid >> 5;
  const int g = lane >> 2, t = lane & 3;
  const int b = blockIdx.y;

  // decode (qt, c): qt has (qt+4)>>2 chunks; 144 CTAs per batch
  int cx = blockIdx.x, qt = 0, c = 0;
  {
    int cum = 0;
    for (;;) {
      int ncq = (qt + 4) >> 2;
      if (cx < cum + ncq) { c = cx - cum; break; }
      cum += ncq;
      qt++;
    }
  }
  const int tv0 = c * 4;                        // 128-key tile index
  const int nt = min(tv0 + 4, qt + 1) - tv0;

  const int wq0 = qt * 128 + (w << 4);
  const size_t bT = (size_t)b * T_;
  const uint32_t* vtw = (const uint32_t*)g_vt;

  // staging geometry: K 1024 f4 (4/thread), V 1024 f4 (4/thread)
  const int krow = tid >> 1, kf4 = (tid & 1) << 2;   // 2 threads/key-row
  const int vrow = tid >> 2, vf4 = (tid & 3) << 2;   // 4 threads/h-row

  auto stage = [&](int tv, int st) {
    const int s0 = tv << 7;
    const uint32_t kb = smb + (st * AT_ST) * 4;
    const uint32_t vb = kb + AT_KS * 4;
    const uint32_t* ksrc = &g_k[(bT + s0 + krow) * 32 + (kf4 << 2)];
#pragma unroll
    for (int i = 0; i < 4; i++)
      CP_ASYNC16(kb + (krow * AT_KW + (kf4 << 2) + (i << 2)) * 4,
                 ksrc + (i << 2));
    const uint32_t* vsrc =
        &vtw[((size_t)b * H_ + vrow) * 2048 + (s0 >> 1) + (vf4 << 2)];
#pragma unroll
    for (int i = 0; i < 4; i++)
      CP_ASYNC16(vb + (vrow * AT_VW + (vf4 << 2) + (i << 2)) * 4,
                 vsrc + (i << 2));
    CP_COMMIT();
  };

  // Q A-fragments from permuted g_q: LDG.64 gives (a0,a2) / (a1,a3)
  uint32_t qf[4][4];
  {
    const uint32_t* qb = &g_q[(bT + wq0) * 32];
#pragma unroll
    for (int ks = 0; ks < 4; ks++) {
      uint2 lo = *(const uint2*)&qb[g * 32 + (ks << 3) + (t << 1)];
      uint2 hi = *(const uint2*)&qb[(g + 8) * 32 + (ks << 3) + (t << 1)];
      qf[ks][0] = lo.x; qf[ks][1] = hi.x; qf[ks][2] = lo.y; qf[ks][3] = hi.y;
    }
  }

  float oacc[8][4] = {};
  float l0 = 0.f, l1 = 0.f;

  stage(tv0, 0);
  for (int ii = 0; ii < nt; ii++) {
    const int st = ii & 1;
    if (ii + 1 < nt) { stage(tv0 + ii + 1, st ^ 1); CP_WAIT(1); }
    else CP_WAIT(0);
    __syncthreads();

    const uint32_t* Kf = sm + st * AT_ST;
    const uint32_t* Vf = Kf + AT_KS;
    const int s0 = (tv0 + ii) << 7;
    const bool maskt = (s0 + 127 > wq0);

#pragma unroll
    for (int nbb = 0; nbb < 8; nbb++) {
      // S: two 8-key blocks (lo: keys 16nbb+0..7, hi: +8..15)
      float sl[4] = {}, sh[4] = {};
#pragma unroll
      for (int ks = 0; ks < 4; ks++) {
        uint2 kl = *(const uint2*)&Kf[((nbb << 4) + g) * AT_KW +
                                      (ks << 3) + (t << 1)];
        mma16(sl, qf[ks], kl);
        uint2 kh = *(const uint2*)&Kf[((nbb << 4) + 8 + g) * AT_KW +
                                      (ks << 3) + (t << 1)];
        mma16(sh, qf[ks], kh);
      }

      // P = exp(S) (+ causal mask), accumulate l
      float pl0, pl1, pl2, pl3, ph0, ph1, ph2, ph3;
      if (maskt) {
        int colL = s0 + (nbb << 4) + (t << 1);
        int colH = colL + 8;
        int r0 = wq0 + g, r1 = wq0 + 8 + g;
        pl0 = (colL <= r0) ? __expf(sl[0]) : 0.f;
        pl1 = (colL + 1 <= r0) ? __expf(sl[1]) : 0.f;
        pl2 = (colL <= r1) ? __expf(sl[2]) : 0.f;
        pl3 = (colL + 1 <= r1) ? __expf(sl[3]) : 0.f;
        ph0 = (colH <= r0) ? __expf(sh[0]) : 0.f;
        ph1 = (colH + 1 <= r0) ? __expf(sh[1]) : 0.f;
        ph2 = (colH <= r1) ? __expf(sh[2]) : 0.f;
        ph3 = (colH + 1 <= r1) ? __expf(sh[3]) : 0.f;
      } else {
        pl0 = __expf(sl[0]); pl1 = __expf(sl[1]);
        pl2 = __expf(sl[2]); pl3 = __expf(sl[3]);
        ph0 = __expf(sh[0]); ph1 = __expf(sh[1]);
        ph2 = __expf(sh[2]); ph3 = __expf(sh[3]);
      }
      l0 += (pl0 + pl1) + (ph0 + ph1);
      l1 += (pl2 + pl3) + (ph2 + ph3);

      // fp16 A-frag of P: C-frag col pairs pack directly into half2 words
      uint32_t pa[4];
      pa[0] = pack2(pl0, pl1);
      pa[1] = pack2(pl2, pl3);
      pa[2] = pack2(ph0, ph1);
      pa[3] = pack2(ph2, ph3);

      // O += P_super V_super (k=16 keys per MMA)
#pragma unroll
      for (int hb = 0; hb < 8; hb++) {
        uint2 vv = *(const uint2*)&Vf[((hb << 3) + g) * AT_VW +
                                      (nbb << 3) + (t << 1)];
        mma16(oacc[hb], pa, vv);
      }
    }
    __syncthreads();
  }

  // reduce l across the quad
#pragma unroll
  for (int off = 1; off <= 2; off <<= 1) {
    l0 += __shfl_xor_sync(~0u, l0, off);
    l1 += __shfl_xor_sync(~0u, l1, off);
  }
  if (t == 0) {
    g_lpart[c][bT + wq0 + g] = l0;
    g_lpart[c][bT + wq0 + 8 + g] = l1;
  }

#pragma unroll
  for (int hb = 0; hb < 8; hb++) {
    int h = (hb << 3) + (t << 1);
    *(float2*)&g_opart[c][(bT + wq0 + g) * H_ + h] =
        make_float2(oacc[hb][0], oacc[hb][1]);
    *(float2*)&g_opart[c][(bT + wq0 + 8 + g) * H_ + h] =
        make_float2(oacc[hb][2], oacc[hb][3]);
  }
}

// ---------------------------------------------------------------------------
// Combine: out = (sum_c O~_c) / (sum_c l_c). Grid (256, 4), 256 threads:
// thread -> (row = tid>>4 of 16, one float4 of h). 262K threads; per thread
// nc independent float4 loads + nc lpart loads -> latency fully covered.
// ---------------------------------------------------------------------------
__global__ __launch_bounds__(256) void combine_kernel(float* __restrict__ out) {
  const int b = blockIdx.y;
  const int r0 = blockIdx.x << 4;
  const int qt = r0 >> 7;
  const int nc = (qt + 4) >> 2;
  const int r = r0 + (threadIdx.x >> 4);
  const int h0 = (threadIdx.x & 15) << 2;
  const size_t row = (size_t)(b * T_ + r);

  float L = 0.f;
  float4 a = make_float4(0.f, 0.f, 0.f, 0.f);
  for (int cc = 0; cc < nc; cc++) {
    float4 v = *(const float4*)&g_opart[cc][row * H_ + h0];
    float lv = g_lpart[cc][row];
    a.x += v.x; a.y += v.y; a.z += v.z; a.w += v.w;
    L += lv;
  }
  const float inv = 1.f / L;
  *(float4*)&out[row * H_ + h0] =
      make_float4(a.x * inv, a.y * inv, a.z * inv, a.w * inv);
}

extern "C" void kernel_launch(void* const* d_in, const int* in_sizes, int n_in,
                              void* d_out, int out_size) {
  const float* x = (const float*)d_in[0];
  const float* Wq = (const float*)d_in[1];
  const float* Wk = (const float*)d_in[2];
  const float* Wv = (const float*)d_in[3];
  float* out = (float*)d_out;

  cudaFuncSetAttribute(proj_kernel, cudaFuncAttributeMaxDynamicSharedMemorySize,
                       PJ_SMEM);
  cudaFuncSetAttribute(attn_kernel, cudaFuncAttributeMaxDynamicSharedMemorySize,
                       AT_SMEM);

  wcvt_kernel<<<48, 256>>>(Wq, Wk, Wv);
  proj_kernel<<<dim3((B_ * T_) / 64), 256, PJ_SMEM>>>(x);
  attn_kernel<<<dim3(144, B_), 256, AT_SMEM>>>();
  combine_kernel<<<dim3(T_ / 16, B_), 256>>>(out);
}

// round 13
// speedup vs baseline: 1.0789x; 1.0789x over previous
#include <cuda_runtime.h>
#include <cuda_fp16.h>
#include <cstdint>

#define B_ 4
#define T_ 4096
#define C_ 1024
#define H_ 64
#define NCH 8  // max split-K chunks per q-tile

// Scratch (static __device__, allocation-free per harness rules).
// All fp16 operand arrays use word-level pair permutation: within each group
// of 8 half2-words (16 halves), logical word j is stored at 2j (j<4) / 2j-7.
__device__ uint32_t g_q[B_ * T_ * 32];   // q/32, half2 words [row][32]
__device__ uint32_t g_k[B_ * T_ * 32];   // k, half2 words [key][32]
__device__ __half g_vt[(size_t)B_ * H_ * T_];  // v transposed [b][h][s]
__device__ uint32_t g_wt[3][H_ * (C_ / 2)];    // W^T [n][k-words]
__device__ float g_opart[NCH][B_ * T_ * H_];   // partial O per chunk (fp32)
__device__ float g_lpart[NCH][B_ * T_];        // exp-sum per chunk

// ---------------------------------------------------------------------------
// Helpers (generic PTX — compiles on compute_103 target)
// ---------------------------------------------------------------------------
__device__ __forceinline__ uint32_t smem_u32(const void* p) {
  uint32_t a;
  asm("{ .reg .u64 t; cvta.to.shared.u64 t, %1; cvt.u32.u64 %0, t; }"
      : "=r"(a) : "l"(p));
  return a;
}
__device__ __forceinline__ uint32_t pack2(float lo, float hi) {
  __half2 h = __floats2half2_rn(lo, hi);
  return *reinterpret_cast<uint32_t*>(&h);
}
__device__ __forceinline__ int pj(int j) {  // word perm within 8-word group
  return (j < 4) ? (j << 1) : ((j << 1) - 7);
}
#define CP_ASYNC16(dst, src) \
  asm volatile("cp.async.cg.shared.global [%0], [%1], 16;" :: "r"(dst), "l"(src))
#define CP_COMMIT() asm volatile("cp.async.commit_group;" ::: "memory")
#define CP_WAIT(n) asm volatile("cp.async.wait_group %0;" :: "n"(n) : "memory")

// D(m16n8) += A(m16k16,row) * B(k16n8,col), fp16 inputs, f32 accum.
// A: a0=(g, k=2t,2t+1) a1=(g+8, same) a2=(g, 2t+8,2t+9) a3=(g+8, same)
// B: b0=(k=2t,2t+1, n=g) b1=(k=2t+8,2t+9, n=g)
// C: c0=(g,2t) c1=(g,2t+1) c2=(g+8,2t) c3=(g+8,2t+1)   [g=lane>>2, t=lane&3]
__device__ __forceinline__ void mma16(float* c, const uint32_t* a, uint2 b) {
  asm volatile(
      "mma.sync.aligned.m16n8k16.row.col.f32.f16.f16.f32 "
      "{%0,%1,%2,%3}, {%4,%5,%6,%7}, {%8,%9}, {%0,%1,%2,%3};"
      : "+f"(c[0]), "+f"(c[1]), "+f"(c[2]), "+f"(c[3])
      : "r"(a[0]), "r"(a[1]), "r"(a[2]), "r"(a[3]), "r"(b.x), "r"(b.y));
}

// ---------------------------------------------------------------------------
// Weight prep: g_wt[wsel][n][kw] = fp16(W[k][n]), pair-permuted words.
// ---------------------------------------------------------------------------
__global__ __launch_bounds__(256) void wcvt_kernel(
    const float* __restrict__ Wq, const float* __restrict__ Wk,
    const float* __restrict__ Wv) {
  int idx = blockIdx.x * 256 + threadIdx.x;
  int wsel = idx >> 12;
  int rem = idx & 4095;
  int gk = rem >> 6;     // k-group (16 k's)
  int n = rem & 63;
  const float* W = (wsel == 0) ? Wq : ((wsel == 1) ? Wk : Wv);
  uint32_t wl[8];
#pragma unroll
  for (int j = 0; j < 8; j++)
    wl[j] = pack2(W[(size_t)(gk * 16 + 2 * j) * H_ + n],
                  W[(size_t)(gk * 16 + 2 * j + 1) * H_ + n]);
  uint4 lo = make_uint4(wl[0], wl[4], wl[1], wl[5]);
  uint4 hi = make_uint4(wl[2], wl[6], wl[3], wl[7]);
  *(uint4*)&g_wt[wsel][(size_t)n * 512 + gk * 8] = lo;
  *(uint4*)&g_wt[wsel][(size_t)n * 512 + gk * 8 + 4] = hi;
}

// ---------------------------------------------------------------------------
// Projection: {q,k,v} = x @ {Wq,Wk,Wv}, fp16 m16n8k16. CTA 64(M) x 192(N),
// K chunks of 64 (16 chunks). W via cp.async from g_wt; x reg-prefetched,
// converted+packed once per element. 8 warps = 2(M) x 4(N); warp tile 32x48.
// Smem word stride 40 (≡8 mod 32 -> conflict-free LDS.64 per 16-lane phase).
// ---------------------------------------------------------------------------
#define SSTR 40
#define PJ_XS (64 * SSTR)           // 2560 u32
#define PJ_ST (PJ_XS + 192 * SSTR) // 10240 u32 per stage
#define PJ_SMEM (2 * PJ_ST * 4)    // 81920 B

__global__ __launch_bounds__(256, 2) void proj_kernel(
    const float* __restrict__ x) {
  extern __shared__ uint32_t sm[];
  const uint32_t smb = smem_u32(sm);

  const int tid = threadIdx.x;
  const int lane = tid & 31;
  const int w = tid >> 5;
  const int g = lane >> 2, t = lane & 3;
  const int wm = (w & 1) << 5;   // warp M offset (0,32)
  const int wn = (w >> 1) * 48;  // warp N offset (0,48,96,144)
  const int row0 = blockIdx.x * 64;

  // x staging: thread -> (row, 16k-group gi); 4 float4 per chunk
  const int xrow = tid >> 2, gi = tid & 3;
  const float* xsrc = &x[(size_t)(row0 + xrow) * C_ + gi * 16];
  // W staging: 192 n x 8 u4 = 1536 u4, 6 per thread
  int wofs[6];
  const uint32_t* wsrc[6];
#pragma unroll
  for (int i = 0; i < 6; i++) {
    int fi = tid + (i << 8);
    int n = fi >> 3;
    int w4 = (fi & 7) << 2;
    wofs[i] = n * SSTR + w4;
    wsrc[i] = &g_wt[n >> 6][(size_t)(n & 63) * 512 + w4];
  }

  float4 xv[4];
  auto prefx = [&](int ch) {
#pragma unroll
    for (int i = 0; i < 4; i++)
      xv[i] = *(const float4*)(xsrc + (ch << 6) + (i << 2));
  };
  auto stageW = [&](int ch, int st) {
    const uint32_t wb = smb + (st * PJ_ST + PJ_XS) * 4;
#pragma unroll
    for (int i = 0; i < 6; i++)
      CP_ASYNC16(wb + wofs[i] * 4, wsrc[i] + (ch << 5));
    CP_COMMIT();
  };

  float acc[2][6][4] = {};

  stageW(0, 0);
  prefx(0);
  for (int ch = 0; ch < 16; ch++) {
    const int st = ch & 1;
    uint32_t* Xs = sm + st * PJ_ST;
    uint32_t* Ws = Xs + PJ_XS;
    // convert+pack x once, store permuted
    {
      uint32_t wl[8];
      wl[0] = pack2(xv[0].x, xv[0].y); wl[1] = pack2(xv[0].z, xv[0].w);
      wl[2] = pack2(xv[1].x, xv[1].y); wl[3] = pack2(xv[1].z, xv[1].w);
      wl[4] = pack2(xv[2].x, xv[2].y); wl[5] = pack2(xv[2].z, xv[2].w);
      wl[6] = pack2(xv[3].x, xv[3].y); wl[7] = pack2(xv[3].z, xv[3].w);
      *(uint4*)&Xs[xrow * SSTR + gi * 8] =
          make_uint4(wl[0], wl[4], wl[1], wl[5]);
      *(uint4*)&Xs[xrow * SSTR + gi * 8 + 4] =
          make_uint4(wl[2], wl[6], wl[3], wl[7]);
    }
    CP_WAIT(0);  // W(ch) landed
    __syncthreads();
    if (ch + 1 < 16) {
      stageW(ch + 1, st ^ 1);  // safe: all warps passed barrier
      prefx(ch + 1);
    }

#pragma unroll
    for (int ks = 0; ks < 4; ks++) {
      uint32_t a[2][4];
#pragma unroll
      for (int mb = 0; mb < 2; mb++) {
        int r = wm + (mb << 4) + g;
        uint2 lo = *(const uint2*)&Xs[r * SSTR + (ks << 3) + (t << 1)];
        uint2 hi = *(const uint2*)&Xs[(r + 8) * SSTR + (ks << 3) + (t << 1)];
        a[mb][0] = lo.x; a[mb][1] = hi.x; a[mb][2] = lo.y; a[mb][3] = hi.y;
      }
#pragma unroll
      for (int nb = 0; nb < 6; nb++) {
        uint2 bb = *(const uint2*)&Ws[(wn + (nb << 3) + g) * SSTR +
                                      (ks << 3) + (t << 1)];
        mma16(acc[0][nb], a[0], bb);
        mma16(acc[1][nb], a[1], bb);
      }
    }
  }

  // Epilogue
#pragma unroll
  for (int mb = 0; mb < 2; mb++) {
#pragma unroll
    for (int nb = 0; nb < 6; nb++) {
      int n = wn + (nb << 3) + (t << 1);
      int r = row0 + wm + (mb << 4) + g;
      float c0 = acc[mb][nb][0], c1 = acc[mb][nb][1];
      float c2 = acc[mb][nb][2], c3 = acc[mb][nb][3];
      if (n < 64) {  // q: scaled 1/32
        int wl = n >> 1;
        int sw = (wl & ~7) + pj(wl & 7);
        g_q[(size_t)r * 32 + sw] = pack2(c0 * 0.03125f, c1 * 0.03125f);
        g_q[(size_t)(r + 8) * 32 + sw] = pack2(c2 * 0.03125f, c3 * 0.03125f);
      } else if (n < 128) {  // k
        int wl = (n - 64) >> 1;
        int sw = (wl & ~7) + pj(wl & 7);
        g_k[(size_t)r * 32 + sw] = pack2(c0, c1);
        g_k[(size_t)(r + 8) * 32 + sw] = pack2(c2, c3);
      } else {  // v transposed [b][h][s], permuted s-words
        int h = n - 128;
        int b = r >> 12, s = r & (T_ - 1);
        int wl = s >> 1, sw = (wl & ~7) + pj(wl & 7);
        int s2 = s + 8, wl2 = s2 >> 1, sw2 = (wl2 & ~7) + pj(wl2 & 7);
        size_t hb0 = ((size_t)b * H_ + h) * 2048;
        size_t hb1 = ((size_t)b * H_ + h + 1) * 2048;
        g_vt[(hb0 + sw) * 2 + (s & 1)] = __float2half_rn(c0);
        g_vt[(hb1 + sw) * 2 + (s & 1)] = __float2half_rn(c1);
        g_vt[(hb0 + sw2) * 2 + (s2 & 1)] = __float2half_rn(c2);
        g_vt[(hb1 + sw2) * 2 + (s2 & 1)] = __float2half_rn(c3);
      }
    }
  }
}

// ---------------------------------------------------------------------------
// Split-K causal attention, fp16 m16n8k16, cp.async 3-STAGE pipelined KV.
// CTA: 128 q-rows (8 warps x 16 rows). KV tiles of 64 keys; chunks of 8
// tiles (512 keys; grid 144 x 4). Two tile-loads always in flight
// (CP_WAIT(1) leaves the newer group pending); ONE __syncthreads per tile.
// Per 16-key superblock: 8 S-MMA -> exp/mask -> pack half2 (C-frag pairs ARE
// fp16 A-frag words) -> 8 O-MMA (k=16).
// ---------------------------------------------------------------------------
#define AT_KS (64 * SSTR)            // 2560 u32
#define AT_ST (2 * AT_KS)            // 5120 u32 per stage (K + V)
#define AT_SMEM (3 * AT_ST * 4)      // 61440 B

__global__ __launch_bounds__(256, 2) void attn_kernel() {
  extern __shared__ uint32_t sm[];
  const uint32_t smb = smem_u32(sm);

  const int tid = threadIdx.x;
  const int lane = tid & 31;
  const int w = tid >> 5;
  const int g = lane >> 2, t = lane & 3;
  const int b = blockIdx.y;

  // decode (qt, c): qt has (2qt+9)>>3 chunks; 144 CTAs per batch
  int cx = blockIdx.x, qt = 0, c = 0;
  {
    int cum = 0;
    for (;;) {
      int ncq = (2 * qt + 9) >> 3;
      if (cx < cum + ncq) { c = cx - cum; break; }
      cum += ncq;
      qt++;
    }
  }
  const int tv0 = c * 8;
  const int nt = min(tv0 + 8, 2 * qt + 2) - tv0;

  const int wq0 = qt * 128 + (w << 4);
  const size_t bT = (size_t)b * T_;

  const int srow = tid >> 2, sw4 = (tid & 3) << 2;  // staging geometry
  const uint32_t* vtw = (const uint32_t*)g_vt;

  auto stage = [&](int tv, int st) {
    const int s0 = tv << 6;
    const uint32_t kb = smb + (st * AT_ST) * 4;
    const uint32_t vb = kb + AT_KS * 4;
    // K: 64 keys x 32 words; 2 u4/thread
    CP_ASYNC16(kb + (srow * SSTR + sw4) * 4,
               &g_k[(bT + s0 + srow) * 32 + sw4]);
    CP_ASYNC16(kb + (srow * SSTR + sw4 + 16) * 4,
               &g_k[(bT + s0 + srow) * 32 + sw4 + 16]);
    // V: 64 h x 32 s-words; 2 u4/thread
    const uint32_t* vsrc = &vtw[((size_t)b * H_ + srow) * 2048 + (s0 >> 1)];
    CP_ASYNC16(vb + (srow * SSTR + sw4) * 4, vsrc + sw4);
    CP_ASYNC16(vb + (srow * SSTR + sw4 + 16) * 4, vsrc + sw4 + 16);
    CP_COMMIT();
  };

  // Q A-fragments from permuted g_q: LDG.64 gives (a0,a2) / (a1,a3)
  uint32_t qf[4][4];
  {
    const uint32_t* qb = &g_q[(bT + wq0) * 32];
#pragma unroll
    for (int ks = 0; ks < 4; ks++) {
      uint2 lo = *(const uint2*)&qb[g * 32 + (ks << 3) + (t << 1)];
      uint2 hi = *(const uint2*)&qb[(g + 8) * 32 + (ks << 3) + (t << 1)];
      qf[ks][0] = lo.x; qf[ks][1] = hi.x; qf[ks][2] = lo.y; qf[ks][3] = hi.y;
    }
  }

  float oacc[8][4] = {};
  float l0 = 0.f, l1 = 0.f;

  stage(tv0, 0);
  if (nt > 1) stage(tv0 + 1, 1);
  int st = 0;
  for (int ii = 0; ii < nt; ii++) {
    if (ii + 1 < nt) CP_WAIT(1);  // tile ii landed; ii+1 stays in flight
    else CP_WAIT(0);
    __syncthreads();  // all threads' tile-ii data visible; buffer (ii+2)%3 free
    if (ii + 2 < nt) stage(tv0 + ii + 2, (st + 2 > 2) ? (st - 1) : (st + 2));

    const uint32_t* Kf = sm + st * AT_ST;
    const uint32_t* Vf = Kf + AT_KS;
    const int s0 = (tv0 + ii) << 6;
    const bool maskt = (s0 + 63 > wq0);

#pragma unroll
    for (int nbb = 0; nbb < 4; nbb++) {
      // S: two 8-key blocks (lo: keys 16nbb+0..7, hi: +8..15)
      float sl[4] = {}, sh[4] = {};
#pragma unroll
      for (int ks = 0; ks < 4; ks++) {
        uint2 kl = *(const uint2*)&Kf[((nbb << 4) + g) * SSTR +
                                      (ks << 3) + (t << 1)];
        mma16(sl, qf[ks], kl);
        uint2 kh = *(const uint2*)&Kf[((nbb << 4) + 8 + g) * SSTR +
                                      (ks << 3) + (t << 1)];
        mma16(sh, qf[ks], kh);
      }

      // P = exp(S) (+ causal mask), accumulate l
      float pl0, pl1, pl2, pl3, ph0, ph1, ph2, ph3;
      if (maskt) {
        int colL = s0 + (nbb << 4) + (t << 1);
        int colH = colL + 8;
        int r0 = wq0 + g, r1 = wq0 + 8 + g;
        pl0 = (colL <= r0) ? __expf(sl[0]) : 0.f;
        pl1 = (colL + 1 <= r0) ? __expf(sl[1]) : 0.f;
        pl2 = (colL <= r1) ? __expf(sl[2]) : 0.f;
        pl3 = (colL + 1 <= r1) ? __expf(sl[3]) : 0.f;
        ph0 = (colH <= r0) ? __expf(sh[0]) : 0.f;
        ph1 = (colH + 1 <= r0) ? __expf(sh[1]) : 0.f;
        ph2 = (colH <= r1) ? __expf(sh[2]) : 0.f;
        ph3 = (colH + 1 <= r1) ? __expf(sh[3]) : 0.f;
      } else {
        pl0 = __expf(sl[0]); pl1 = __expf(sl[1]);
        pl2 = __expf(sl[2]); pl3 = __expf(sl[3]);
        ph0 = __expf(sh[0]); ph1 = __expf(sh[1]);
        ph2 = __expf(sh[2]); ph3 = __expf(sh[3]);
      }
      l0 += (pl0 + pl1) + (ph0 + ph1);
      l1 += (pl2 + pl3) + (ph2 + ph3);

      // fp16 A-frag of P: C-frag col pairs pack directly into half2 words
      uint32_t pa[4];
      pa[0] = pack2(pl0, pl1);
      pa[1] = pack2(pl2, pl3);
      pa[2] = pack2(ph0, ph1);
      pa[3] = pack2(ph2, ph3);

      // O += P_super V_super (k=16 keys per MMA)
#pragma unroll
      for (int hb = 0; hb < 8; hb++) {
        uint2 vv = *(const uint2*)&Vf[((hb << 3) + g) * SSTR +
                                      (nbb << 3) + (t << 1)];
        mma16(oacc[hb], pa, vv);
      }
    }
    st = (st == 2) ? 0 : (st + 1);
  }

  // reduce l across the quad
#pragma unroll
  for (int off = 1; off <= 2; off <<= 1) {
    l0 += __shfl_xor_sync(~0u, l0, off);
    l1 += __shfl_xor_sync(~0u, l1, off);
  }
  if (t == 0) {
    g_lpart[c][bT + wq0 + g] = l0;
    g_lpart[c][bT + wq0 + 8 + g] = l1;
  }

#pragma unroll
  for (int hb = 0; hb < 8; hb++) {
    int h = (hb << 3) + (t << 1);
    *(float2*)&g_opart[c][(bT + wq0 + g) * H_ + h] =
        make_float2(oacc[hb][0], oacc[hb][1]);
    *(float2*)&g_opart[c][(bT + wq0 + 8 + g) * H_ + h] =
        make_float2(oacc[hb][2], oacc[hb][3]);
  }
}

// ---------------------------------------------------------------------------
// Combine: out = (sum_c O~_c) / (sum_c l_c). Grid (256, 4), 256 threads:
// thread -> (row, one float4 of h); nc independent loads per thread.
// ---------------------------------------------------------------------------
__global__ __launch_bounds__(256) void combine_kernel(float* __restrict__ out) {
  const int b = blockIdx.y;
  const int r0 = blockIdx.x << 4;
  const int qt = r0 >> 7;
  const int nc = (2 * qt + 9) >> 3;
  const int r = r0 + (threadIdx.x >> 4);
  const int h0 = (threadIdx.x & 15) << 2;
  const size_t row = (size_t)(b * T_ + r);

  float L = 0.f;
  float4 a = make_float4(0.f, 0.f, 0.f, 0.f);
  for (int cc = 0; cc < nc; cc++) {
    float4 v = *(const float4*)&g_opart[cc][row * H_ + h0];
    float lv = g_lpart[cc][row];
    a.x += v.x; a.y += v.y; a.z += v.z; a.w += v.w;
    L += lv;
  }
  const float inv = 1.f / L;
  *(float4*)&out[row * H_ + h0] =
      make_float4(a.x * inv, a.y * inv, a.z * inv, a.w * inv);
}

extern "C" void kernel_launch(void* const* d_in, const int* in_sizes, int n_in,
                              void* d_out, int out_size) {
  const float* x = (const float*)d_in[0];
  const float* Wq = (const float*)d_in[1];
  const float* Wk = (const float*)d_in[2];
  const float* Wv = (const float*)d_in[3];
  float* out = (float*)d_out;

  cudaFuncSetAttribute(proj_kernel, cudaFuncAttributeMaxDynamicSharedMemorySize,
                       PJ_SMEM);
  cudaFuncSetAttribute(attn_kernel, cudaFuncAttributeMaxDynamicSharedMemorySize,
                       AT_SMEM);

  wcvt_kernel<<<48, 256>>>(Wq, Wk, Wv);
  proj_kernel<<<dim3((B_ * T_) / 64), 256, PJ_SMEM>>>(x);
  attn_kernel<<<dim3(144, B_), 256, AT_SMEM>>>();
  combine_kernel<<<dim3(T_ / 16, B_), 256>>>(out);
}